// round 3
// baseline (speedup 1.0000x reference)
#include <cuda_runtime.h>
#include <cuda_bf16.h>

#define D 128
#define R 32            // rows (edges/nodes) per block
#define PAD 36          // padded row stride in floats (avoids worst bank conflicts, keeps 16B align)
#define EPSV 1e-5f

// Scratch (alloc-free: __device__ globals)
__device__ float g_agg[80000 * D];
__device__ float g_h1[80000 * D];

// ---------------------------------------------------------------------------
// Packed 2xfp32 helpers (Blackwell FFMA2 — only reachable via PTX f32x2)
// ---------------------------------------------------------------------------
__device__ __forceinline__ unsigned long long ffma2(unsigned long long a,
                                                    unsigned long long b,
                                                    unsigned long long c) {
    unsigned long long d;
    asm("fma.rn.f32x2 %0, %1, %2, %3;" : "=l"(d) : "l"(a), "l"(b), "l"(c));
    return d;
}
__device__ __forceinline__ unsigned long long pack2(float lo, float hi) {
    unsigned long long d;
    asm("mov.b64 %0, {%1, %2};" : "=l"(d) : "f"(lo), "f"(hi));
    return d;
}

union Acc {
    float              f[R];
    unsigned long long u[R / 2];
    float4             v4[R / 4];
};

// ---------------------------------------------------------------------------
// GEMM fragment: acc[r] = sum_k xs[k][r] * W[k*128 + tid] + bias
// xs is [K][PAD] in shared (row-pair values contiguous -> f32x2 lanes).
// Each of the 128 threads owns one output feature for all R rows.
// ---------------------------------------------------------------------------
template <int K>
__device__ __forceinline__ void gemm_col(const float* __restrict__ xs,
                                         const float* __restrict__ W,
                                         float bias, Acc& acc) {
    unsigned long long bb = pack2(bias, bias);
#pragma unroll
    for (int i = 0; i < R / 2; i++) acc.u[i] = bb;

    const float* wp = W + threadIdx.x;
#pragma unroll 2
    for (int k = 0; k < K; k++) {
        float w = __ldg(wp + k * D);
        unsigned long long w2 = pack2(w, w);
        const ulonglong2* xv = (const ulonglong2*)(xs + k * PAD);
#pragma unroll
        for (int q = 0; q < R / 4; q++) {
            ulonglong2 v = xv[q];
            acc.u[2 * q + 0] = ffma2(v.x, w2, acc.u[2 * q + 0]);
            acc.u[2 * q + 1] = ffma2(v.y, w2, acc.u[2 * q + 1]);
        }
    }
}

// Transposed store: xs[tid][0..R-1] = acc (pre- or post-LN activations)
__device__ __forceinline__ void store_rows(float* __restrict__ xs, const Acc& acc) {
    float4* dst = (float4*)(xs + threadIdx.x * PAD);
#pragma unroll
    for (int q = 0; q < R / 4; q++) dst[q] = acc.v4[q];
}

// LN stats over the 128-feature dim for R rows. xs = [128][PAD] pre-activations.
// Warp w handles rows w*8 .. w*8+7.
__device__ __forceinline__ void ln_stats(const float* __restrict__ xs,
                                         float2* __restrict__ stats) {
    int wid = threadIdx.x >> 5, lane = threadIdx.x & 31;
#pragma unroll
    for (int rr = 0; rr < R / 4; rr++) {
        int r = wid * (R / 4) + rr;
        float s = 0.f, s2 = 0.f;
#pragma unroll
        for (int j = 0; j < 4; j++) {
            float p = xs[(lane + 32 * j) * PAD + r];
            s += p;
            s2 = fmaf(p, p, s2);
        }
#pragma unroll
        for (int o = 16; o > 0; o >>= 1) {
            s  += __shfl_xor_sync(0xffffffffu, s,  o);
            s2 += __shfl_xor_sync(0xffffffffu, s2, o);
        }
        if (lane == 0) {
            float m = s * (1.0f / 128.0f);
            float v = s2 * (1.0f / 128.0f) - m * m;
            stats[r] = make_float2(m, rsqrtf(v + EPSV));
        }
    }
}

// Apply LN + ReLU in registers: y = relu((acc-m)*rinv*g + beta)
__device__ __forceinline__ void ln_apply(Acc& acc, const float2* __restrict__ stats,
                                         float gv, float bev) {
#pragma unroll
    for (int r = 0; r < R; r++) {
        float2 st = stats[r];
        float y = fmaf((acc.f[r] - st.x) * st.y, gv, bev);
        acc.f[r] = fmaxf(y, 0.f);
    }
}

#define SMEM_FLOATS (384 * PAD)
#define SMEM_BYTES  (SMEM_FLOATS * 4 + R * 8)

// ---------------------------------------------------------------------------
// Edge kernel: per edge  y2 = relu(LN(relu(LN([h[src],bond] @ W1 + b1)) @ W2 + b2))
//              atomicAdd(agg[dst], y2)
// ---------------------------------------------------------------------------
__global__ __launch_bounds__(128)
void edge_kernel(const float* __restrict__ h,
                 const float* __restrict__ bond,
                 const int* __restrict__ src,
                 const int* __restrict__ dst,
                 const float* __restrict__ W1, const float* __restrict__ b1,
                 const float* __restrict__ g1, const float* __restrict__ be1,
                 const float* __restrict__ W2, const float* __restrict__ b2,
                 const float* __restrict__ g2, const float* __restrict__ be2,
                 float* __restrict__ agg, int E) {
    extern __shared__ float smem[];
    float*  xsA   = smem;                     // [256][PAD]
    float*  xsB   = smem + 256 * PAD;         // [128][PAD]
    float2* stats = (float2*)(smem + SMEM_FLOATS);

    int tid = threadIdx.x;
    long long e0 = (long long)blockIdx.x * R;
    int nvalid = (int)min((long long)R, (long long)E - e0);

    // Gather [h[src], bond] -> xsA (transposed: feature-major rows)
#pragma unroll
    for (int r = 0; r < R; r++) {
        float hv = 0.f, bv = 0.f;
        if (r < nvalid) {
            long long e = e0 + r;
            int s = src[e];
            hv = h[(long long)s * D + tid];
            bv = bond[e * D + tid];
        }
        xsA[tid * PAD + r] = hv;
        xsA[(128 + tid) * PAD + r] = bv;
    }
    __syncthreads();

    Acc acc;
    // Layer 1 (K=256)
    gemm_col<256>(xsA, W1, b1[tid], acc);
    store_rows(xsB, acc);                 // pre-LN
    __syncthreads();
    ln_stats(xsB, stats);
    __syncthreads();
    ln_apply(acc, stats, g1[tid], be1[tid]);
    store_rows(xsB, acc);                 // final y1
    __syncthreads();

    // Layer 2 (K=128)
    gemm_col<128>(xsB, W2, b2[tid], acc);
    __syncthreads();
    store_rows(xsA, acc);                 // pre-LN scratch
    __syncthreads();
    ln_stats(xsA, stats);
    __syncthreads();
    ln_apply(acc, stats, g2[tid], be2[tid]);

    // Scatter-add
    for (int r = 0; r < nvalid; r++) {
        int dn = dst[e0 + r];
        atomicAdd(&agg[(long long)dn * D + tid], acc.f[r]);
    }
}

// ---------------------------------------------------------------------------
// Node kernel: f = relu(LN(relu(LN([ax,agg] @ sW1+sb1)) @ sW2+sb2))
//              out = relu(LN([ax,f] @ hW + hb))
// ---------------------------------------------------------------------------
__global__ __launch_bounds__(128)
void node_kernel(const float* __restrict__ ax,
                 const float* __restrict__ aggin,
                 const float* __restrict__ sW1, const float* __restrict__ sb1,
                 const float* __restrict__ sg1, const float* __restrict__ sbe1,
                 const float* __restrict__ sW2, const float* __restrict__ sb2,
                 const float* __restrict__ sg2, const float* __restrict__ sbe2,
                 const float* __restrict__ hW, const float* __restrict__ hb,
                 const float* __restrict__ hg, const float* __restrict__ hbe,
                 float* __restrict__ out, int N) {
    extern __shared__ float smem[];
    float*  xsA   = smem;                     // [256][PAD]: [0..127]=ax, [128..255]=agg then f
    float*  xsB   = smem + 256 * PAD;         // [128][PAD]
    float2* stats = (float2*)(smem + SMEM_FLOATS);

    int tid = threadIdx.x;
    long long n0 = (long long)blockIdx.x * R;
    int nvalid = (int)min((long long)R, (long long)N - n0);

#pragma unroll
    for (int r = 0; r < R; r++) {
        float av = 0.f, gvv = 0.f;
        if (r < nvalid) {
            long long n = n0 + r;
            av = ax[n * D + tid];
            gvv = aggin[n * D + tid];
        }
        xsA[tid * PAD + r] = av;
        xsA[(128 + tid) * PAD + r] = gvv;
    }
    __syncthreads();

    Acc acc;
    // Layer 1 (K=256): [ax, agg] @ sW1
    gemm_col<256>(xsA, sW1, sb1[tid], acc);
    store_rows(xsB, acc);
    __syncthreads();
    ln_stats(xsB, stats);
    __syncthreads();
    ln_apply(acc, stats, sg1[tid], sbe1[tid]);
    store_rows(xsB, acc);
    __syncthreads();

    // Layer 2 (K=128): f = ... @ sW2
    gemm_col<128>(xsB, sW2, sb2[tid], acc);
    __syncthreads();
    store_rows(xsA + 128 * PAD, acc);     // pre-LN scratch (agg region, done with it)
    __syncthreads();
    ln_stats(xsA + 128 * PAD, stats);
    __syncthreads();
    ln_apply(acc, stats, sg2[tid], sbe2[tid]);
    store_rows(xsA + 128 * PAD, acc);     // final f -> [ax, f] now staged in xsA
    __syncthreads();

    // Layer 3 (K=256): head
    gemm_col<256>(xsA, hW, hb[tid], acc);
    __syncthreads();
    store_rows(xsB, acc);
    __syncthreads();
    ln_stats(xsB, stats);
    __syncthreads();
    ln_apply(acc, stats, hg[tid], hbe[tid]);

    for (int r = 0; r < nvalid; r++) {
        out[(n0 + r) * D + tid] = acc.f[r];
    }
}

// ---------------------------------------------------------------------------
// kernel_launch (input order per metadata, same as round 1)
// ---------------------------------------------------------------------------
extern "C" void kernel_launch(void* const* d_in, const int* in_sizes, int n_in,
                              void* d_out, int out_size) {
    const float* subtree_h_top = (const float*)d_in[0];
    const float* atom_x_1      = (const float*)d_in[1];
    const float* atom_x_0      = (const float*)d_in[2];
    const float* bond_x_2      = (const float*)d_in[3];
    const float* bond_x_1      = (const float*)d_in[4];
    const float* branch_W1     = (const float*)d_in[5];
    const float* branch_b1     = (const float*)d_in[6];
    const float* branch_g1     = (const float*)d_in[7];
    const float* branch_beta1  = (const float*)d_in[8];
    const float* branch_W2     = (const float*)d_in[9];
    const float* branch_b2     = (const float*)d_in[10];
    const float* branch_g2     = (const float*)d_in[11];
    const float* branch_beta2  = (const float*)d_in[12];
    const float* sub_W1        = (const float*)d_in[13];
    const float* sub_b1        = (const float*)d_in[14];
    const float* sub_g1        = (const float*)d_in[15];
    const float* sub_beta1     = (const float*)d_in[16];
    const float* sub_W2        = (const float*)d_in[17];
    const float* sub_b2        = (const float*)d_in[18];
    const float* sub_g2        = (const float*)d_in[19];
    const float* sub_beta2     = (const float*)d_in[20];
    const float* head_W        = (const float*)d_in[21];
    const float* head_b        = (const float*)d_in[22];
    const float* head_g        = (const float*)d_in[23];
    const float* head_beta     = (const float*)d_in[24];
    const int*   src_2         = (const int*)d_in[25];
    const int*   dst_2         = (const int*)d_in[26];
    const int*   src_1         = (const int*)d_in[27];
    const int*   dst_1         = (const int*)d_in[28];

    const int n2 = in_sizes[0] / D;
    const int n1 = in_sizes[1] / D;
    const int n0 = in_sizes[2] / D;

    float* agg; cudaGetSymbolAddress((void**)&agg, g_agg);
    float* h1;  cudaGetSymbolAddress((void**)&h1,  g_h1);
    float* out = (float*)d_out;

    static bool attr_done = false;
    if (!attr_done) {
        cudaFuncSetAttribute(edge_kernel, cudaFuncAttributeMaxDynamicSharedMemorySize, SMEM_BYTES);
        cudaFuncSetAttribute(node_kernel, cudaFuncAttributeMaxDynamicSharedMemorySize, SMEM_BYTES);
        attr_done = true;
    }

    const int W1_STRIDE = 256 * D;
    const int W2_STRIDE = 128 * D;
    const int V_STRIDE  = D;

    // ---------------- level 0 (k=2): n2 edges -> n1 nodes ----------------
    cudaMemsetAsync(agg, 0, (size_t)n1 * D * sizeof(float));
    edge_kernel<<<(n2 + R - 1) / R, 128, SMEM_BYTES>>>(
        subtree_h_top, bond_x_2, src_2, dst_2,
        branch_W1, branch_b1, branch_g1, branch_beta1,
        branch_W2, branch_b2, branch_g2, branch_beta2,
        agg, n2);
    node_kernel<<<(n1 + R - 1) / R, 128, SMEM_BYTES>>>(
        atom_x_1, agg,
        sub_W1, sub_b1, sub_g1, sub_beta1,
        sub_W2, sub_b2, sub_g2, sub_beta2,
        head_W, head_b, head_g, head_beta,
        h1, n1);

    // ---------------- level 1 (k=1): n1 edges -> n0 nodes ----------------
    cudaMemsetAsync(agg, 0, (size_t)n0 * D * sizeof(float));
    edge_kernel<<<(n1 + R - 1) / R, 128, SMEM_BYTES>>>(
        h1, bond_x_1, src_1, dst_1,
        branch_W1 + W1_STRIDE, branch_b1 + V_STRIDE, branch_g1 + V_STRIDE, branch_beta1 + V_STRIDE,
        branch_W2 + W2_STRIDE, branch_b2 + V_STRIDE, branch_g2 + V_STRIDE, branch_beta2 + V_STRIDE,
        agg, n1);
    node_kernel<<<(n0 + R - 1) / R, 128, SMEM_BYTES>>>(
        atom_x_0, agg,
        sub_W1 + W1_STRIDE, sub_b1 + V_STRIDE, sub_g1 + V_STRIDE, sub_beta1 + V_STRIDE,
        sub_W2 + W2_STRIDE, sub_b2 + V_STRIDE, sub_g2 + V_STRIDE, sub_beta2 + V_STRIDE,
        head_W + W1_STRIDE, head_b + V_STRIDE, head_g + V_STRIDE, head_beta + V_STRIDE,
        out, n0);
}

// round 5
// speedup vs baseline: 3.0872x; 3.0872x over previous
#include <cuda_runtime.h>
#include <cuda_fp16.h>
#include <cstdint>

#define D 128
#define EPSV 1e-5f

// ---------------- smem layout (byte offsets into dynamic smem) ----------------
#define AS       264            // fp16 elems per A row (256 cols + 8 pad)
#define A_H      0u             // 128 x 264 fp16 = 67584 B
#define A_L      67584u         // lo tile, same layout
#define WBUF     135168u        // 2 bufs x (hi 10240 + lo 10240)
#define WSTRIDE  40             // fp16 per W row (32 k + 8 pad)
#define WBUFSZ   20480u
#define SM_BIAS  176128u
#define SM_G     176640u
#define SM_BE    177152u
#define SM_SRC   177664u
#define SM_DST   178176u
#define SMEM_DYN 178688u
// fp32 stage (128 x 132) aliases the A region (only used after all MMAs of a kernel)
#define STG_STRIDE 132

// ---------------- scratch (alloc-free) ----------------
__device__ float g_agg[80000 * D];
__device__ float g_h1[80000 * D];
// prepped weights: per level 524288 B; chunk = 16KB ([n=128][k=32] fp16 hi 8KB + lo 8KB)
__device__ __align__(16) unsigned char g_Wprep[2 * 524288];
#define OFF_BW1 0u
#define OFF_BW2 131072u
#define OFF_SW1 196608u
#define OFF_SW2 327680u
#define OFF_HW  393216u
#define WLEVEL  524288u

// ---------------- PTX helpers (base-ISA only: works on compute_103) ----------------
__device__ __forceinline__ uint32_t smem_u32(const void* p) {
    uint32_t a;
    asm("{ .reg .u64 t; cvta.to.shared.u64 t, %1; cvt.u32.u64 %0, t; }" : "=r"(a) : "l"(p));
    return a;
}
#define LDSM4(r, addr) \
    asm volatile("ldmatrix.sync.aligned.m8n8.x4.shared.b16 {%0,%1,%2,%3}, [%4];" \
                 : "=r"((r)[0]), "=r"((r)[1]), "=r"((r)[2]), "=r"((r)[3]) : "r"(addr))
#define MMA16816(dd, a, b0, b1) \
    asm volatile("mma.sync.aligned.m16n8k16.row.col.f32.f16.f16.f32 " \
                 "{%0,%1,%2,%3},{%4,%5,%6,%7},{%8,%9},{%0,%1,%2,%3};" \
                 : "+f"((dd)[0]), "+f"((dd)[1]), "+f"((dd)[2]), "+f"((dd)[3]) \
                 : "r"((a)[0]), "r"((a)[1]), "r"((a)[2]), "r"((a)[3]), "r"(b0), "r"(b1))

// ---------------- fp16 hi/lo split ----------------
__device__ __forceinline__ void split2(float a, float b, uint32_t& hi, uint32_t& lo) {
    __half2 h = __floats2half2_rn(a, b);
    hi = *reinterpret_cast<uint32_t*>(&h);
    __half2 l = __floats2half2_rn(a - __low2float(h), b - __high2float(h));
    lo = *reinterpret_cast<uint32_t*>(&l);
}

// ---------------- gather: 128 fp32 cols -> A hi/lo fp16 tiles at col0 ----------------
__device__ __forceinline__ void gather128(unsigned char* sm, const float4* __restrict__ src,
                                          const int* idx, long long row0, int col0,
                                          int nvalid, int t) {
    int r = t >> 1, half = t & 1;
    int cbase = col0 + half * 64;
    bool ok = r < nvalid;
    long long sr = idx ? (ok ? (long long)idx[r] : 0) : (row0 + r);
    const float4* p = src + sr * 32 + half * 16;
#pragma unroll
    for (int j = 0; j < 16; j++) {
        float4 v = ok ? __ldg(p + j) : make_float4(0.f, 0.f, 0.f, 0.f);
        uint32_t h0, l0, h1, l1;
        split2(v.x, v.y, h0, l0);
        split2(v.z, v.w, h1, l1);
        uint32_t off = (uint32_t)(r * AS + cbase + j * 4) * 2u;
        *(uint2*)(sm + A_H + off) = make_uint2(h0, h1);
        *(uint2*)(sm + A_L + off) = make_uint2(l0, l1);
    }
}

// ---------------- one GEMM layer: K = NC*32, A cols start at kbase ----------------
// D[128x128] accumulated in registers (warp w owns rows w*16..w*16+15).
__device__ __forceinline__ void run_layer(unsigned char* sm, uint32_t smb,
                                          const unsigned char* __restrict__ w,
                                          int NC, int kbase, float* d,
                                          int t, int lane, int warp) {
#pragma unroll
    for (int i = 0; i < 64; i++) d[i] = 0.f;

    int n = t >> 1, s = t & 1;
    int bi = n * 4 + s * 2;
    int4 v0, v1, v2, v3;
    {   // preload chunk 0 -> buf0
        const int4* g = (const int4*)w;
        v0 = __ldg(g + bi); v1 = __ldg(g + bi + 1);
        v2 = __ldg(g + 512 + bi); v3 = __ldg(g + 512 + bi + 1);
        unsigned char* dh = sm + WBUF + (uint32_t)(n * 80 + s * 32);
        *(int4*)dh = v0; *(int4*)(dh + 16) = v1;
        *(int4*)(dh + 10240) = v2; *(int4*)(dh + 10240 + 16) = v3;
    }
    const uint32_t aconst = smb + A_H +
        (uint32_t)((warp * 16 + (lane & 7) + ((lane >> 3) & 1) * 8) * AS + (lane >> 4) * 8) * 2u;
    const uint32_t bconst = (uint32_t)((((lane >> 4) * 8 + (lane & 7)) * WSTRIDE +
                                        ((lane >> 3) & 1) * 8) * 2);

#pragma unroll 1
    for (int c = 0; c < NC; c++) {
        __syncthreads();
        bool more = (c + 1) < NC;
        if (more) {
            const int4* g = (const int4*)(w + (size_t)(c + 1) * 16384u);
            v0 = __ldg(g + bi); v1 = __ldg(g + bi + 1);
            v2 = __ldg(g + 512 + bi); v3 = __ldg(g + 512 + bi + 1);
        }
        uint32_t wbase = smb + WBUF + (uint32_t)(c & 1) * WBUFSZ + bconst;
#pragma unroll
        for (int ks = 0; ks < 2; ks++) {
            uint32_t ah[4], al[4];
            uint32_t aaddr = aconst + (uint32_t)(kbase + c * 32 + ks * 16) * 2u;
            LDSM4(ah, aaddr);
            LDSM4(al, aaddr + A_L);
#pragma unroll
            for (int g8 = 0; g8 < 8; g8++) {
                uint32_t bh[4], bl[4];
                uint32_t baddr = wbase + (uint32_t)(g8 * 16 * WSTRIDE + ks * 16) * 2u;
                LDSM4(bh, baddr);
                LDSM4(bl, baddr + 10240u);
                float* d0 = d + g8 * 8;
                float* d1 = d + g8 * 8 + 4;
                MMA16816(d0, ah, bh[0], bh[1]);
                MMA16816(d0, ah, bl[0], bl[1]);
                MMA16816(d0, al, bh[0], bh[1]);
                MMA16816(d1, ah, bh[2], bh[3]);
                MMA16816(d1, ah, bl[2], bl[3]);
                MMA16816(d1, al, bh[2], bh[3]);
            }
        }
        if (more) {
            unsigned char* dh = sm + WBUF + (uint32_t)((c + 1) & 1) * WBUFSZ +
                                (uint32_t)(n * 80 + s * 32);
            *(int4*)dh = v0; *(int4*)(dh + 16) = v1;
            *(int4*)(dh + 10240) = v2; *(int4*)(dh + 10240 + 16) = v3;
        }
    }
}

// ---------------- epilogue: bias + LN + ReLU on register D-frags ----------------
// mode 0: write fp16 hi/lo back into A tiles at column dstcol.
// mode 1: write fp32 into stage (aliases A region).
__device__ __forceinline__ void epilogue(unsigned char* sm, float* d,
                                         const float* __restrict__ b,
                                         const float* __restrict__ g,
                                         const float* __restrict__ be,
                                         int mode, int dstcol, int t, int lane, int warp) {
    float* bs  = (float*)(sm + SM_BIAS);
    float* gs  = (float*)(sm + SM_G);
    float* bes = (float*)(sm + SM_BE);
    if (t < 128) { bs[t] = b[t]; gs[t] = g[t]; bes[t] = be[t]; }
    __syncthreads();

    int r0 = warp * 16 + (lane >> 2);
    int r1 = r0 + 8;
    float s0 = 0.f, q0 = 0.f, s1 = 0.f, q1 = 0.f;
#pragma unroll
    for (int nt = 0; nt < 16; nt++) {
        int c0 = nt * 8 + (lane & 3) * 2;
        float x0 = d[nt * 4 + 0] + bs[c0];
        float x1 = d[nt * 4 + 1] + bs[c0 + 1];
        float x2 = d[nt * 4 + 2] + bs[c0];
        float x3 = d[nt * 4 + 3] + bs[c0 + 1];
        d[nt * 4 + 0] = x0; d[nt * 4 + 1] = x1; d[nt * 4 + 2] = x2; d[nt * 4 + 3] = x3;
        s0 += x0 + x1; q0 += x0 * x0 + x1 * x1;
        s1 += x2 + x3; q1 += x2 * x2 + x3 * x3;
    }
    s0 += __shfl_xor_sync(0xffffffffu, s0, 1); s0 += __shfl_xor_sync(0xffffffffu, s0, 2);
    q0 += __shfl_xor_sync(0xffffffffu, q0, 1); q0 += __shfl_xor_sync(0xffffffffu, q0, 2);
    s1 += __shfl_xor_sync(0xffffffffu, s1, 1); s1 += __shfl_xor_sync(0xffffffffu, s1, 2);
    q1 += __shfl_xor_sync(0xffffffffu, q1, 1); q1 += __shfl_xor_sync(0xffffffffu, q1, 2);
    float m0 = s0 * (1.f / 128.f), m1 = s1 * (1.f / 128.f);
    float rv0 = rsqrtf(q0 * (1.f / 128.f) - m0 * m0 + EPSV);
    float rv1 = rsqrtf(q1 * (1.f / 128.f) - m1 * m1 + EPSV);

    float* stg = (float*)sm;
#pragma unroll
    for (int nt = 0; nt < 16; nt++) {
        int c0 = nt * 8 + (lane & 3) * 2;
        float y0 = fmaxf(fmaf((d[nt * 4 + 0] - m0) * rv0, gs[c0],     bes[c0]),     0.f);
        float y1 = fmaxf(fmaf((d[nt * 4 + 1] - m0) * rv0, gs[c0 + 1], bes[c0 + 1]), 0.f);
        float y2 = fmaxf(fmaf((d[nt * 4 + 2] - m1) * rv1, gs[c0],     bes[c0]),     0.f);
        float y3 = fmaxf(fmaf((d[nt * 4 + 3] - m1) * rv1, gs[c0 + 1], bes[c0 + 1]), 0.f);
        if (mode == 0) {
            uint32_t h, l;
            uint32_t o0 = (uint32_t)(r0 * AS + dstcol + c0) * 2u;
            split2(y0, y1, h, l);
            *(uint32_t*)(sm + A_H + o0) = h;
            *(uint32_t*)(sm + A_L + o0) = l;
            uint32_t o1 = (uint32_t)(r1 * AS + dstcol + c0) * 2u;
            split2(y2, y3, h, l);
            *(uint32_t*)(sm + A_H + o1) = h;
            *(uint32_t*)(sm + A_L + o1) = l;
        } else {
            *(float2*)(stg + r0 * STG_STRIDE + c0) = make_float2(y0, y1);
            *(float2*)(stg + r1 * STG_STRIDE + c0) = make_float2(y2, y3);
        }
    }
}

// ---------------- edge kernel ----------------
__global__ __launch_bounds__(256, 1)
void edge_kernel(const float* __restrict__ h, const float* __restrict__ bond,
                 const int* __restrict__ src, const int* __restrict__ dst,
                 const unsigned char* __restrict__ wlev,
                 const float* __restrict__ b1, const float* __restrict__ g1, const float* __restrict__ be1,
                 const float* __restrict__ b2, const float* __restrict__ g2, const float* __restrict__ be2,
                 float* __restrict__ agg, int E) {
    extern __shared__ __align__(16) unsigned char sm[];
    uint32_t smb = smem_u32(sm);
    int t = threadIdx.x, lane = t & 31, warp = t >> 5;
    long long e0 = (long long)blockIdx.x * 128;
    int nvalid = (int)min(128ll, (long long)E - e0);

    int* ssm = (int*)(sm + SM_SRC);
    int* dsm = (int*)(sm + SM_DST);
    if (t < 128) {
        ssm[t] = (t < nvalid) ? src[e0 + t] : 0;
        dsm[t] = (t < nvalid) ? dst[e0 + t] : 0;
    }
    __syncthreads();

    gather128(sm, (const float4*)h, ssm, 0, 0, nvalid, t);
    gather128(sm, (const float4*)bond, nullptr, e0, 128, nvalid, t);

    float d[64];
    run_layer(sm, smb, wlev + OFF_BW1, 8, 0, d, t, lane, warp);
    epilogue(sm, d, b1, g1, be1, 0, 0, t, lane, warp);
    run_layer(sm, smb, wlev + OFF_BW2, 4, 0, d, t, lane, warp);
    epilogue(sm, d, b2, g2, be2, 1, 0, t, lane, warp);
    __syncthreads();

    const float* stg = (const float*)sm;
    int col = t & 127;
    for (int r = t >> 7; r < nvalid; r += 2)
        atomicAdd(&agg[(size_t)dsm[r] * 128 + col], stg[r * STG_STRIDE + col]);
}

// ---------------- node kernel ----------------
__global__ __launch_bounds__(256, 1)
void node_kernel(const float* __restrict__ ax, const float* __restrict__ aggin,
                 const unsigned char* __restrict__ wlev,
                 const float* __restrict__ sb1, const float* __restrict__ sg1, const float* __restrict__ sbe1,
                 const float* __restrict__ sb2, const float* __restrict__ sg2, const float* __restrict__ sbe2,
                 const float* __restrict__ hb, const float* __restrict__ hg, const float* __restrict__ hbe,
                 float* __restrict__ out, int N) {
    extern __shared__ __align__(16) unsigned char sm[];
    uint32_t smb = smem_u32(sm);
    int t = threadIdx.x, lane = t & 31, warp = t >> 5;
    long long n0 = (long long)blockIdx.x * 128;
    int nvalid = (int)min(128ll, (long long)N - n0);

    gather128(sm, (const float4*)ax, nullptr, n0, 0, nvalid, t);
    gather128(sm, (const float4*)aggin, nullptr, n0, 128, nvalid, t);

    float d[64];
    run_layer(sm, smb, wlev + OFF_SW1, 8, 0, d, t, lane, warp);
    epilogue(sm, d, sb1, sg1, sbe1, 0, 128, t, lane, warp);   // f1 -> cols 128..255 (keep ax)
    run_layer(sm, smb, wlev + OFF_SW2, 4, 128, d, t, lane, warp);
    epilogue(sm, d, sb2, sg2, sbe2, 0, 128, t, lane, warp);   // f2 -> cols 128..255
    run_layer(sm, smb, wlev + OFF_HW, 8, 0, d, t, lane, warp);
    epilogue(sm, d, hb, hg, hbe, 1, 0, t, lane, warp);
    __syncthreads();

    const float* stg = (const float*)sm;
    int col = t & 127;
    for (int r = t >> 7; r < nvalid; r += 2)
        out[(n0 + r) * 128 + col] = stg[r * STG_STRIDE + col];
}

// ---------------- weight prep: fp32 W[K][128] -> chunked W^T fp16 hi/lo ----------------
__global__ void prep_kernel(const float* __restrict__ bW1, const float* __restrict__ bW2,
                            const float* __restrict__ sW1, const float* __restrict__ sW2,
                            const float* __restrict__ hW) {
    int level = blockIdx.y, cid = blockIdx.x, t = threadIdx.x;
    const float* W; int c; uint32_t off; int K;
    if (cid < 8)       { W = bW1; c = cid;      off = OFF_BW1; K = 256; }
    else if (cid < 12) { W = bW2; c = cid - 8;  off = OFF_BW2; K = 128; }
    else if (cid < 20) { W = sW1; c = cid - 12; off = OFF_SW1; K = 256; }
    else if (cid < 24) { W = sW2; c = cid - 20; off = OFF_SW2; K = 128; }
    else               { W = hW;  c = cid - 24; off = OFF_HW;  K = 256; }

    const float* wsrc = W + (size_t)level * K * 128 + (size_t)c * 32 * 128;
    unsigned char* dstb = g_Wprep + (size_t)level * WLEVEL + off + (size_t)c * 16384u;
    for (int kk = 0; kk < 32; kk++) {
        float x = wsrc[kk * 128 + t];            // W[k][n], n = t
        __half hi = __float2half_rn(x);
        __half lo = __float2half_rn(x - __half2float(hi));
        uint32_t o = (uint32_t)(t * 32 + kk) * 2u;   // [n][k]
        *(__half*)(dstb + o)         = hi;
        *(__half*)(dstb + 8192u + o) = lo;
    }
}

// ---------------- kernel_launch ----------------
extern "C" void kernel_launch(void* const* d_in, const int* in_sizes, int n_in,
                              void* d_out, int out_size) {
    const float* subtree_h_top = (const float*)d_in[0];
    const float* atom_x_1      = (const float*)d_in[1];
    const float* atom_x_0      = (const float*)d_in[2];
    const float* bond_x_2      = (const float*)d_in[3];
    const float* bond_x_1      = (const float*)d_in[4];
    const float* branch_W1     = (const float*)d_in[5];
    const float* branch_b1     = (const float*)d_in[6];
    const float* branch_g1     = (const float*)d_in[7];
    const float* branch_beta1  = (const float*)d_in[8];
    const float* branch_W2     = (const float*)d_in[9];
    const float* branch_b2     = (const float*)d_in[10];
    const float* branch_g2     = (const float*)d_in[11];
    const float* branch_beta2  = (const float*)d_in[12];
    const float* sub_W1        = (const float*)d_in[13];
    const float* sub_b1        = (const float*)d_in[14];
    const float* sub_g1        = (const float*)d_in[15];
    const float* sub_beta1     = (const float*)d_in[16];
    const float* sub_W2        = (const float*)d_in[17];
    const float* sub_b2        = (const float*)d_in[18];
    const float* sub_g2        = (const float*)d_in[19];
    const float* sub_beta2     = (const float*)d_in[20];
    const float* head_W        = (const float*)d_in[21];
    const float* head_b        = (const float*)d_in[22];
    const float* head_g        = (const float*)d_in[23];
    const float* head_beta     = (const float*)d_in[24];
    const int*   src_2         = (const int*)d_in[25];
    const int*   dst_2         = (const int*)d_in[26];
    const int*   src_1         = (const int*)d_in[27];
    const int*   dst_1         = (const int*)d_in[28];

    const int n2 = in_sizes[0] / D;
    const int n1 = in_sizes[1] / D;
    const int n0 = in_sizes[2] / D;

    float* agg; cudaGetSymbolAddress((void**)&agg, g_agg);
    float* h1;  cudaGetSymbolAddress((void**)&h1,  g_h1);
    unsigned char* wprep; cudaGetSymbolAddress((void**)&wprep, g_Wprep);
    float* out = (float*)d_out;

    static bool attr_done = false;
    if (!attr_done) {
        cudaFuncSetAttribute(edge_kernel, cudaFuncAttributeMaxDynamicSharedMemorySize, SMEM_DYN);
        cudaFuncSetAttribute(node_kernel, cudaFuncAttributeMaxDynamicSharedMemorySize, SMEM_DYN);
        attr_done = true;
    }

    const int V = D;

    prep_kernel<<<dim3(32, 2), 128>>>(branch_W1, branch_W2, sub_W1, sub_W2, head_W);

    // level 0: n2 edges -> n1 nodes
    cudaMemsetAsync(agg, 0, (size_t)n1 * D * sizeof(float));
    edge_kernel<<<(n2 + 127) / 128, 256, SMEM_DYN>>>(
        subtree_h_top, bond_x_2, src_2, dst_2, wprep,
        branch_b1, branch_g1, branch_beta1,
        branch_b2, branch_g2, branch_beta2, agg, n2);
    node_kernel<<<(n1 + 127) / 128, 256, SMEM_DYN>>>(
        atom_x_1, agg, wprep,
        sub_b1, sub_g1, sub_beta1,
        sub_b2, sub_g2, sub_beta2,
        head_b, head_g, head_beta, h1, n1);

    // level 1: n1 edges -> n0 nodes
    cudaMemsetAsync(agg, 0, (size_t)n0 * D * sizeof(float));
    edge_kernel<<<(n1 + 127) / 128, 256, SMEM_DYN>>>(
        h1, bond_x_1, src_1, dst_1, wprep + WLEVEL,
        branch_b1 + V, branch_g1 + V, branch_beta1 + V,
        branch_b2 + V, branch_g2 + V, branch_beta2 + V, agg, n1);
    node_kernel<<<(n0 + 127) / 128, 256, SMEM_DYN>>>(
        atom_x_0, agg, wprep + WLEVEL,
        sub_b1 + V, sub_g1 + V, sub_beta1 + V,
        sub_b2 + V, sub_g2 + V, sub_beta2 + V,
        head_b + V, head_g + V, head_beta + V, out, n0);
}

// round 6
// speedup vs baseline: 3.1913x; 1.0337x over previous
#include <cuda_runtime.h>
#include <cuda_fp16.h>
#include <cstdint>

#define D 128
#define EPSV 1e-5f

// ---------------- smem layout (byte offsets into dynamic smem) ----------------
#define AS       264            // fp16 elems per A row (256 cols + 8 pad)
#define A_H      0u             // 128 x 264 fp16 = 67584 B
#define A_L      67584u         // lo tile, same layout
#define WBUF     135168u        // 2 bufs x (hi 10240 + lo 10240)
#define WSTRIDE  40             // fp16 per W row (32 k + 8 pad)
#define WBUFSZ   20480u
#define SM_BIAS  176128u
#define SM_G     176640u
#define SM_BE    177152u
#define SM_SRC   177664u
#define SM_DST   178176u
#define SM_PART  178688u        // 128 rows x 2 halves x float2 = 2048 B
#define SMEM_DYN 180736u
// fp32 stage (128 x 132) aliases the A region (only used after all MMAs of a kernel)
#define STG_STRIDE 132

// ---------------- scratch (alloc-free) ----------------
__device__ float g_agg[80000 * D];
__device__ float g_h1[80000 * D];
// prepped weights: per level 524288 B; chunk = 16KB ([n=128][k=32] fp16 hi 8KB + lo 8KB)
__device__ __align__(16) unsigned char g_Wprep[2 * 524288];
#define OFF_BW1 0u
#define OFF_BW2 131072u
#define OFF_SW1 196608u
#define OFF_SW2 327680u
#define OFF_HW  393216u
#define WLEVEL  524288u

// ---------------- PTX helpers (base ISA: valid on compute_103) ----------------
__device__ __forceinline__ uint32_t smem_u32(const void* p) {
    uint32_t a;
    asm("{ .reg .u64 t; cvta.to.shared.u64 t, %1; cvt.u32.u64 %0, t; }" : "=r"(a) : "l"(p));
    return a;
}
#define LDSM4(r, addr) \
    asm volatile("ldmatrix.sync.aligned.m8n8.x4.shared.b16 {%0,%1,%2,%3}, [%4];" \
                 : "=r"((r)[0]), "=r"((r)[1]), "=r"((r)[2]), "=r"((r)[3]) : "r"(addr))
#define MMA16816(dd, a, b0, b1) \
    asm volatile("mma.sync.aligned.m16n8k16.row.col.f32.f16.f16.f32 " \
                 "{%0,%1,%2,%3},{%4,%5,%6,%7},{%8,%9},{%0,%1,%2,%3};" \
                 : "+f"((dd)[0]), "+f"((dd)[1]), "+f"((dd)[2]), "+f"((dd)[3]) \
                 : "r"((a)[0]), "r"((a)[1]), "r"((a)[2]), "r"((a)[3]), "r"(b0), "r"(b1))

// ---------------- fp16 hi/lo split ----------------
__device__ __forceinline__ void split2(float a, float b, uint32_t& hi, uint32_t& lo) {
    __half2 h = __floats2half2_rn(a, b);
    hi = *reinterpret_cast<uint32_t*>(&h);
    __half2 l = __floats2half2_rn(a - __low2float(h), b - __high2float(h));
    lo = *reinterpret_cast<uint32_t*>(&l);
}

// ---------------- gather: 128 fp32 cols -> A hi/lo fp16 tiles at col0 (512 thr) ----------------
__device__ __forceinline__ void gather128(unsigned char* sm, const float4* __restrict__ src,
                                          const int* idx, long long row0, int col0,
                                          int nvalid, int t) {
    int r = t >> 2, q = t & 3;
    int cbase = col0 + q * 32;
    bool ok = r < nvalid;
    long long sr = idx ? (ok ? (long long)idx[r] : 0) : (row0 + r);
    const float4* p = src + sr * 32 + q * 8;
#pragma unroll
    for (int j = 0; j < 8; j++) {
        float4 v = ok ? __ldg(p + j) : make_float4(0.f, 0.f, 0.f, 0.f);
        uint32_t h0, l0, h1, l1;
        split2(v.x, v.y, h0, l0);
        split2(v.z, v.w, h1, l1);
        uint32_t off = (uint32_t)(r * AS + cbase + j * 4) * 2u;
        *(uint2*)(sm + A_H + off) = make_uint2(h0, h1);
        *(uint2*)(sm + A_L + off) = make_uint2(l0, l1);
    }
}

// ---------------- one GEMM layer: K = NC*32, A cols start at kbase ----------------
// 16 warps: warp tile = 16 rows x 64 cols. d[32] register accumulators.
__device__ __forceinline__ void run_layer(unsigned char* sm, uint32_t smb,
                                          const unsigned char* __restrict__ w,
                                          int NC, int kbase, float* d,
                                          int t, int lane, int warp) {
#pragma unroll
    for (int i = 0; i < 32; i++) d[i] = 0.f;

    int n = t >> 2, s4 = t & 3;
    int gi = n * 4 + s4;                 // int4 index within 8KB hi image
    int4 vh, vl;
    {   // preload chunk 0 -> buf0
        const int4* g = (const int4*)w;
        vh = __ldg(g + gi); vl = __ldg(g + 512 + gi);
        unsigned char* dh = sm + WBUF + (uint32_t)(n * 80 + s4 * 16);
        *(int4*)dh = vh;
        *(int4*)(dh + 10240) = vl;
    }
    int wrow = (warp & 7) * 16, wcol = (warp >> 3) * 64;
    const uint32_t aconst = smb + A_H +
        (uint32_t)((wrow + (lane & 7) + ((lane >> 3) & 1) * 8) * AS + (lane >> 4) * 8) * 2u;
    const uint32_t bconst = (uint32_t)(((wcol + (lane >> 4) * 8 + (lane & 7)) * WSTRIDE +
                                        ((lane >> 3) & 1) * 8) * 2);

#pragma unroll 1
    for (int c = 0; c < NC; c++) {
        __syncthreads();
        bool more = (c + 1) < NC;
        if (more) {
            const int4* g = (const int4*)(w + (size_t)(c + 1) * 16384u);
            vh = __ldg(g + gi); vl = __ldg(g + 512 + gi);
        }
        uint32_t wbase = smb + WBUF + (uint32_t)(c & 1) * WBUFSZ + bconst;
#pragma unroll
        for (int ks = 0; ks < 2; ks++) {
            uint32_t ah[4], al[4];
            uint32_t aaddr = aconst + (uint32_t)(kbase + c * 32 + ks * 16) * 2u;
            LDSM4(ah, aaddr);
            LDSM4(al, aaddr + A_L);
#pragma unroll
            for (int g8 = 0; g8 < 4; g8++) {
                uint32_t bh[4], bl[4];
                uint32_t baddr = wbase + (uint32_t)(g8 * 16 * WSTRIDE + ks * 16) * 2u;
                LDSM4(bh, baddr);
                LDSM4(bl, baddr + 10240u);
                float* d0 = d + g8 * 8;
                float* d1 = d + g8 * 8 + 4;
                MMA16816(d0, ah, bh[0], bh[1]);
                MMA16816(d1, ah, bh[2], bh[3]);
                MMA16816(d0, ah, bl[0], bl[1]);
                MMA16816(d1, ah, bl[2], bl[3]);
                MMA16816(d0, al, bh[0], bh[1]);
                MMA16816(d1, al, bh[2], bh[3]);
            }
        }
        if (more) {
            unsigned char* dh = sm + WBUF + (uint32_t)((c + 1) & 1) * WBUFSZ +
                                (uint32_t)(n * 80 + s4 * 16);
            *(int4*)dh = vh;
            *(int4*)(dh + 10240) = vl;
        }
    }
}

// ---------------- epilogue: bias + LN + ReLU (cross-warp LN via smem partials) ----------------
// mode 0: write fp16 hi/lo back into A tiles at column dstcol. mode 1: fp32 stage.
__device__ __forceinline__ void epilogue(unsigned char* sm, float* d,
                                         const float* __restrict__ b,
                                         const float* __restrict__ g,
                                         const float* __restrict__ be,
                                         int mode, int dstcol, int t, int lane, int warp) {
    float* bs  = (float*)(sm + SM_BIAS);
    float* gs  = (float*)(sm + SM_G);
    float* bes = (float*)(sm + SM_BE);
    float2* part = (float2*)(sm + SM_PART);
    if (t < 128) { bs[t] = b[t]; gs[t] = g[t]; bes[t] = be[t]; }
    __syncthreads();

    int wrow = (warp & 7) * 16, wcol = (warp >> 3) * 64, half = warp >> 3;
    int r0 = wrow + (lane >> 2);
    int r1 = r0 + 8;
    float s0 = 0.f, q0 = 0.f, s1 = 0.f, q1 = 0.f;
#pragma unroll
    for (int j = 0; j < 8; j++) {
        int c0 = wcol + j * 8 + (lane & 3) * 2;
        float x0 = d[j * 4 + 0] + bs[c0];
        float x1 = d[j * 4 + 1] + bs[c0 + 1];
        float x2 = d[j * 4 + 2] + bs[c0];
        float x3 = d[j * 4 + 3] + bs[c0 + 1];
        d[j * 4 + 0] = x0; d[j * 4 + 1] = x1; d[j * 4 + 2] = x2; d[j * 4 + 3] = x3;
        s0 += x0 + x1; q0 += x0 * x0 + x1 * x1;
        s1 += x2 + x3; q1 += x2 * x2 + x3 * x3;
    }
    s0 += __shfl_xor_sync(0xffffffffu, s0, 1); s0 += __shfl_xor_sync(0xffffffffu, s0, 2);
    q0 += __shfl_xor_sync(0xffffffffu, q0, 1); q0 += __shfl_xor_sync(0xffffffffu, q0, 2);
    s1 += __shfl_xor_sync(0xffffffffu, s1, 1); s1 += __shfl_xor_sync(0xffffffffu, s1, 2);
    q1 += __shfl_xor_sync(0xffffffffu, q1, 1); q1 += __shfl_xor_sync(0xffffffffu, q1, 2);
    if ((lane & 3) == 0) {
        part[r0 * 2 + half] = make_float2(s0, q0);
        part[r1 * 2 + half] = make_float2(s1, q1);
    }
    __syncthreads();

    float2 pa = part[r0 * 2], pb = part[r0 * 2 + 1];
    float sum0 = pa.x + pb.x, qq0 = pa.y + pb.y;
    pa = part[r1 * 2]; pb = part[r1 * 2 + 1];
    float sum1 = pa.x + pb.x, qq1 = pa.y + pb.y;
    float m0 = sum0 * (1.f / 128.f), m1 = sum1 * (1.f / 128.f);
    float rv0 = rsqrtf(qq0 * (1.f / 128.f) - m0 * m0 + EPSV);
    float rv1 = rsqrtf(qq1 * (1.f / 128.f) - m1 * m1 + EPSV);

    float* stg = (float*)sm;
#pragma unroll
    for (int j = 0; j < 8; j++) {
        int c0 = wcol + j * 8 + (lane & 3) * 2;
        float y0 = fmaxf(fmaf((d[j * 4 + 0] - m0) * rv0, gs[c0],     bes[c0]),     0.f);
        float y1 = fmaxf(fmaf((d[j * 4 + 1] - m0) * rv0, gs[c0 + 1], bes[c0 + 1]), 0.f);
        float y2 = fmaxf(fmaf((d[j * 4 + 2] - m1) * rv1, gs[c0],     bes[c0]),     0.f);
        float y3 = fmaxf(fmaf((d[j * 4 + 3] - m1) * rv1, gs[c0 + 1], bes[c0 + 1]), 0.f);
        if (mode == 0) {
            uint32_t h, l;
            uint32_t o0 = (uint32_t)(r0 * AS + dstcol + c0) * 2u;
            split2(y0, y1, h, l);
            *(uint32_t*)(sm + A_H + o0) = h;
            *(uint32_t*)(sm + A_L + o0) = l;
            uint32_t o1 = (uint32_t)(r1 * AS + dstcol + c0) * 2u;
            split2(y2, y3, h, l);
            *(uint32_t*)(sm + A_H + o1) = h;
            *(uint32_t*)(sm + A_L + o1) = l;
        } else {
            *(float2*)(stg + r0 * STG_STRIDE + c0) = make_float2(y0, y1);
            *(float2*)(stg + r1 * STG_STRIDE + c0) = make_float2(y2, y3);
        }
    }
}

// ---------------- edge kernel ----------------
__global__ __launch_bounds__(512, 1)
void edge_kernel(const float* __restrict__ h, const float* __restrict__ bond,
                 const int* __restrict__ src, const int* __restrict__ dst,
                 const unsigned char* __restrict__ wlev,
                 const float* __restrict__ b1, const float* __restrict__ g1, const float* __restrict__ be1,
                 const float* __restrict__ b2, const float* __restrict__ g2, const float* __restrict__ be2,
                 float* __restrict__ agg, int E) {
    extern __shared__ __align__(16) unsigned char sm[];
    uint32_t smb = smem_u32(sm);
    int t = threadIdx.x, lane = t & 31, warp = t >> 5;
    long long e0 = (long long)blockIdx.x * 128;
    int nvalid = (int)min(128ll, (long long)E - e0);

    int* ssm = (int*)(sm + SM_SRC);
    int* dsm = (int*)(sm + SM_DST);
    if (t < 128) {
        ssm[t] = (t < nvalid) ? src[e0 + t] : 0;
        dsm[t] = (t < nvalid) ? dst[e0 + t] : 0;
    }
    __syncthreads();

    gather128(sm, (const float4*)h, ssm, 0, 0, nvalid, t);
    gather128(sm, (const float4*)bond, nullptr, e0, 128, nvalid, t);

    float d[32];
    run_layer(sm, smb, wlev + OFF_BW1, 8, 0, d, t, lane, warp);
    epilogue(sm, d, b1, g1, be1, 0, 0, t, lane, warp);
    run_layer(sm, smb, wlev + OFF_BW2, 4, 0, d, t, lane, warp);
    epilogue(sm, d, b2, g2, be2, 1, 0, t, lane, warp);
    __syncthreads();

    const float* stg = (const float*)sm;
    int col = t & 127;
    for (int r = t >> 7; r < nvalid; r += 4)
        atomicAdd(&agg[(size_t)dsm[r] * 128 + col], stg[r * STG_STRIDE + col]);
}

// ---------------- node kernel ----------------
__global__ __launch_bounds__(512, 1)
void node_kernel(const float* __restrict__ ax, const float* __restrict__ aggin,
                 const unsigned char* __restrict__ wlev,
                 const float* __restrict__ sb1, const float* __restrict__ sg1, const float* __restrict__ sbe1,
                 const float* __restrict__ sb2, const float* __restrict__ sg2, const float* __restrict__ sbe2,
                 const float* __restrict__ hb, const float* __restrict__ hg, const float* __restrict__ hbe,
                 float* __restrict__ out, int N) {
    extern __shared__ __align__(16) unsigned char sm[];
    uint32_t smb = smem_u32(sm);
    int t = threadIdx.x, lane = t & 31, warp = t >> 5;
    long long n0 = (long long)blockIdx.x * 128;
    int nvalid = (int)min(128ll, (long long)N - n0);

    gather128(sm, (const float4*)ax, nullptr, n0, 0, nvalid, t);
    gather128(sm, (const float4*)aggin, nullptr, n0, 128, nvalid, t);

    float d[32];
    run_layer(sm, smb, wlev + OFF_SW1, 8, 0, d, t, lane, warp);
    epilogue(sm, d, sb1, sg1, sbe1, 0, 128, t, lane, warp);   // f1 -> cols 128..255 (keep ax)
    run_layer(sm, smb, wlev + OFF_SW2, 4, 128, d, t, lane, warp);
    epilogue(sm, d, sb2, sg2, sbe2, 0, 128, t, lane, warp);   // f2 -> cols 128..255
    run_layer(sm, smb, wlev + OFF_HW, 8, 0, d, t, lane, warp);
    epilogue(sm, d, hb, hg, hbe, 1, 0, t, lane, warp);
    __syncthreads();

    const float* stg = (const float*)sm;
    int col = t & 127;
    for (int r = t >> 7; r < nvalid; r += 4)
        out[(n0 + r) * 128 + col] = stg[r * STG_STRIDE + col];
}

// ---------------- weight prep: fp32 W[K][128] -> chunked W^T fp16 hi/lo ----------------
__global__ void prep_kernel(const float* __restrict__ bW1, const float* __restrict__ bW2,
                            const float* __restrict__ sW1, const float* __restrict__ sW2,
                            const float* __restrict__ hW) {
    int level = blockIdx.y, cid = blockIdx.x, t = threadIdx.x;
    const float* W; int c; uint32_t off; int K;
    if (cid < 8)       { W = bW1; c = cid;      off = OFF_BW1; K = 256; }
    else if (cid < 12) { W = bW2; c = cid - 8;  off = OFF_BW2; K = 128; }
    else if (cid < 20) { W = sW1; c = cid - 12; off = OFF_SW1; K = 256; }
    else if (cid < 24) { W = sW2; c = cid - 20; off = OFF_SW2; K = 128; }
    else               { W = hW;  c = cid - 24; off = OFF_HW;  K = 256; }

    const float* wsrc = W + (size_t)level * K * 128 + (size_t)c * 32 * 128;
    unsigned char* dstb = g_Wprep + (size_t)level * WLEVEL + off + (size_t)c * 16384u;
    for (int kk = 0; kk < 32; kk++) {
        float x = wsrc[kk * 128 + t];            // W[k][n], n = t
        __half hi = __float2half_rn(x);
        __half lo = __float2half_rn(x - __half2float(hi));
        uint32_t o = (uint32_t)(t * 32 + kk) * 2u;   // [n][k]
        *(__half*)(dstb + o)         = hi;
        *(__half*)(dstb + 8192u + o) = lo;
    }
}

// ---------------- kernel_launch ----------------
extern "C" void kernel_launch(void* const* d_in, const int* in_sizes, int n_in,
                              void* d_out, int out_size) {
    const float* subtree_h_top = (const float*)d_in[0];
    const float* atom_x_1      = (const float*)d_in[1];
    const float* atom_x_0      = (const float*)d_in[2];
    const float* bond_x_2      = (const float*)d_in[3];
    const float* bond_x_1      = (const float*)d_in[4];
    const float* branch_W1     = (const float*)d_in[5];
    const float* branch_b1     = (const float*)d_in[6];
    const float* branch_g1     = (const float*)d_in[7];
    const float* branch_beta1  = (const float*)d_in[8];
    const float* branch_W2     = (const float*)d_in[9];
    const float* branch_b2     = (const float*)d_in[10];
    const float* branch_g2     = (const float*)d_in[11];
    const float* branch_beta2  = (const float*)d_in[12];
    const float* sub_W1        = (const float*)d_in[13];
    const float* sub_b1        = (const float*)d_in[14];
    const float* sub_g1        = (const float*)d_in[15];
    const float* sub_beta1     = (const float*)d_in[16];
    const float* sub_W2        = (const float*)d_in[17];
    const float* sub_b2        = (const float*)d_in[18];
    const float* sub_g2        = (const float*)d_in[19];
    const float* sub_beta2     = (const float*)d_in[20];
    const float* head_W        = (const float*)d_in[21];
    const float* head_b        = (const float*)d_in[22];
    const float* head_g        = (const float*)d_in[23];
    const float* head_beta     = (const float*)d_in[24];
    const int*   src_2         = (const int*)d_in[25];
    const int*   dst_2         = (const int*)d_in[26];
    const int*   src_1         = (const int*)d_in[27];
    const int*   dst_1         = (const int*)d_in[28];

    const int n2 = in_sizes[0] / D;
    const int n1 = in_sizes[1] / D;
    const int n0 = in_sizes[2] / D;

    float* agg; cudaGetSymbolAddress((void**)&agg, g_agg);
    float* h1;  cudaGetSymbolAddress((void**)&h1,  g_h1);
    unsigned char* wprep; cudaGetSymbolAddress((void**)&wprep, g_Wprep);
    float* out = (float*)d_out;

    static bool attr_done = false;
    if (!attr_done) {
        cudaFuncSetAttribute(edge_kernel, cudaFuncAttributeMaxDynamicSharedMemorySize, SMEM_DYN);
        cudaFuncSetAttribute(node_kernel, cudaFuncAttributeMaxDynamicSharedMemorySize, SMEM_DYN);
        attr_done = true;
    }

    const int V = D;

    prep_kernel<<<dim3(32, 2), 128>>>(branch_W1, branch_W2, sub_W1, sub_W2, head_W);

    // level 0: n2 edges -> n1 nodes
    cudaMemsetAsync(agg, 0, (size_t)n1 * D * sizeof(float));
    edge_kernel<<<(n2 + 127) / 128, 512, SMEM_DYN>>>(
        subtree_h_top, bond_x_2, src_2, dst_2, wprep,
        branch_b1, branch_g1, branch_beta1,
        branch_b2, branch_g2, branch_beta2, agg, n2);
    node_kernel<<<(n1 + 127) / 128, 512, SMEM_DYN>>>(
        atom_x_1, agg, wprep,
        sub_b1, sub_g1, sub_beta1,
        sub_b2, sub_g2, sub_beta2,
        head_b, head_g, head_beta, h1, n1);

    // level 1: n1 edges -> n0 nodes
    cudaMemsetAsync(agg, 0, (size_t)n0 * D * sizeof(float));
    edge_kernel<<<(n1 + 127) / 128, 512, SMEM_DYN>>>(
        h1, bond_x_1, src_1, dst_1, wprep + WLEVEL,
        branch_b1 + V, branch_g1 + V, branch_beta1 + V,
        branch_b2 + V, branch_g2 + V, branch_beta2 + V, agg, n1);
    node_kernel<<<(n0 + 127) / 128, 512, SMEM_DYN>>>(
        atom_x_0, agg, wprep + WLEVEL,
        sub_b1 + V, sub_g1 + V, sub_beta1 + V,
        sub_b2 + V, sub_g2 + V, sub_beta2 + V,
        head_b + V, head_g + V, head_beta + V, out, n0);
}